// round 2
// baseline (speedup 1.0000x reference)
#include <cuda_runtime.h>
#include <cstdint>

#define CRF_S 512
#define CRF_B 256
#define CRF_L 128
#define PAD_ID 0
#define START_ID 1

// mask dtype: 0 = int32, 1 = byte(bool/int8), 2 = float32
__device__ int g_mode;

// ---------------------------------------------------------------------------
// Prep: detect mask dtype (deterministic fingerprint) and zero the output.
// Scans only the first B*S/4 32-bit words = 128KB-safe under every candidate
// dtype (byte mode: whole buffer; int32/float: first quarter, enough to see
// the 0x3F800000 float-1.0 pattern at word 0 since lengths >= 1).
// ---------------------------------------------------------------------------
__global__ void crf_prep(const unsigned* __restrict__ masks_w, float* out) {
    __shared__ int flagByte, flagFloat;
    int tid = threadIdx.x;
    if (tid == 0) { flagByte = 0; flagFloat = 0; out[0] = 0.0f; }
    __syncthreads();
    int lb = 0, lf = 0;
    for (int k = tid; k < (CRF_B * CRF_S) / 4; k += blockDim.x) {
        unsigned w = masks_w[k];
        if (w == 0x3F800000u) lf = 1;          // float 1.0 pattern (impossible for byte/int32 here)
        else if (w > 1u) lb = 1;               // byte-packed bools (e.g. 0x01010101) or garbage
    }
    if (lb) atomicOr(&flagByte, 1);
    if (lf) atomicOr(&flagFloat, 1);
    __syncthreads();
    if (tid == 0) g_mode = flagFloat ? 2 : (flagByte ? 1 : 0);
}

// ---------------------------------------------------------------------------
// Main: one warp per batch, two warps (batches) per block sharing one smem
// copy of expT = exp(T). Lane l owns columns j = 4l..4l+3 (float4).
// Per step: m = max(fs); p = exp(fs-m) -> smem (double-buffered, 1 syncwarp);
// dot_j = sum_i p[i]*expT[i][j] via float4 LDS + FFMA;
// fs[j] = emit[t][b][j] + m + log(dot_j).
// Gold path + final partition folded into the same warp.
// ---------------------------------------------------------------------------
__global__ void __launch_bounds__(64) crf_main(
    const float* __restrict__ emit,
    const int*   __restrict__ labels,
    const void*  __restrict__ masks,
    const float* __restrict__ T,
    float* out)
{
    extern __shared__ float sm[];
    float* expTs = sm;                          // 16384 floats (64 KB)
    int tid  = threadIdx.x;
    int warp = tid >> 5;
    int lane = tid & 31;
    float* pbuf = sm + CRF_L * CRF_L + warp * (2 * CRF_L);   // per-warp double buffer

    // Cooperative expT build (both warps)
    for (int idx = tid * 4; idx < CRF_L * CRF_L; idx += 64 * 4) {
        float4 tv = *reinterpret_cast<const float4*>(T + idx);
        float4 ev;
        ev.x = __expf(tv.x); ev.y = __expf(tv.y);
        ev.z = __expf(tv.z); ev.w = __expf(tv.w);
        *reinterpret_cast<float4*>(expTs + idx) = ev;
    }
    __syncthreads();

    int b = blockIdx.x * 2 + warp;              // 128 blocks x 2 warps -> 256 batches

    // ---- length from masks (prefix-structured) ----
    int mode = g_mode;
    int cnt = 0;
    if (mode == 1) {
        const unsigned char* mb = (const unsigned char*)masks + (size_t)b * CRF_S;
        for (int k = lane; k < CRF_S; k += 32) cnt += (mb[k] != 0);
    } else if (mode == 2) {
        const float* mf = (const float*)masks + (size_t)b * CRF_S;
        for (int k = lane; k < CRF_S; k += 32) cnt += (mf[k] != 0.0f);
    } else {
        const int* mi = (const int*)masks + (size_t)b * CRF_S;
        for (int k = lane; k < CRF_S; k += 32) cnt += (mi[k] != 0);
    }
    #pragma unroll
    for (int o = 16; o; o >>= 1) cnt += __shfl_xor_sync(0xffffffffu, cnt, o);
    int len = cnt < 1 ? 1 : cnt;

    // ---- gold path score ----
    float gold = 0.f;
    for (int t = lane; t < len; t += 32) {
        int lab  = labels[b * CRF_S + t];
        int prev = (t == 0) ? START_ID : labels[b * CRF_S + t - 1];
        gold += emit[((size_t)t * CRF_B + b) * CRF_L + lab] + T[prev * CRF_L + lab];
    }
    #pragma unroll
    for (int o = 16; o; o >>= 1) gold += __shfl_xor_sync(0xffffffffu, gold, o);
    int lastlab = labels[b * CRF_S + (len - 1)];
    float ends = T[lastlab * CRF_L + PAD_ID];

    // ---- forward init: fs = emit[0][b] + T[START] ----
    int j0 = lane * 4;
    float4 fs;
    {
        float4 e0 = *reinterpret_cast<const float4*>(emit + (size_t)b * CRF_L + j0);
        float4 t1 = *reinterpret_cast<const float4*>(T + START_ID * CRF_L + j0);
        fs.x = e0.x + t1.x; fs.y = e0.y + t1.y;
        fs.z = e0.z + t1.z; fs.w = e0.w + t1.w;
    }

    // ---- forward scan ----
    float4 e_cur = make_float4(0.f, 0.f, 0.f, 0.f);
    float4 e_next = e_cur;
    if (len > 1)
        e_cur = *reinterpret_cast<const float4*>(emit + ((size_t)CRF_B + b) * CRF_L + j0);
    int buf = 0;
    for (int t = 1; t < len; t++) {
        if (t + 1 < len)   // prefetch next emit row (DRAM latency hidden by dot loop)
            e_next = *reinterpret_cast<const float4*>(
                emit + ((size_t)(t + 1) * CRF_B + b) * CRF_L + j0);

        // per-batch max over fs
        float m = fmaxf(fmaxf(fs.x, fs.y), fmaxf(fs.z, fs.w));
        #pragma unroll
        for (int o = 16; o; o >>= 1) m = fmaxf(m, __shfl_xor_sync(0xffffffffu, m, o));

        // p = exp(fs - m) -> shared (double buffered)
        float4 p;
        p.x = __expf(fs.x - m); p.y = __expf(fs.y - m);
        p.z = __expf(fs.z - m); p.w = __expf(fs.w - m);
        float* pb = pbuf + (buf << 7);
        *reinterpret_cast<float4*>(pb + j0) = p;
        __syncwarp();

        // dot_j = sum_i p[i] * expT[i][j]
        float4 acc; acc.x = acc.y = acc.z = acc.w = 0.f;
        #pragma unroll 8
        for (int i = 0; i < CRF_L; i += 4) {
            float4 pv = *reinterpret_cast<const float4*>(pb + i);   // broadcast
            float4 t0 = *reinterpret_cast<const float4*>(expTs + (i + 0) * CRF_L + j0);
            acc.x += pv.x * t0.x; acc.y += pv.x * t0.y;
            acc.z += pv.x * t0.z; acc.w += pv.x * t0.w;
            float4 t1 = *reinterpret_cast<const float4*>(expTs + (i + 1) * CRF_L + j0);
            acc.x += pv.y * t1.x; acc.y += pv.y * t1.y;
            acc.z += pv.y * t1.z; acc.w += pv.y * t1.w;
            float4 t2 = *reinterpret_cast<const float4*>(expTs + (i + 2) * CRF_L + j0);
            acc.x += pv.z * t2.x; acc.y += pv.z * t2.y;
            acc.z += pv.z * t2.z; acc.w += pv.z * t2.w;
            float4 t3 = *reinterpret_cast<const float4*>(expTs + (i + 3) * CRF_L + j0);
            acc.x += pv.w * t3.x; acc.y += pv.w * t3.y;
            acc.z += pv.w * t3.z; acc.w += pv.w * t3.w;
        }

        fs.x = e_cur.x + m + __logf(acc.x);
        fs.y = e_cur.y + m + __logf(acc.y);
        fs.z = e_cur.z + m + __logf(acc.z);
        fs.w = e_cur.w + m + __logf(acc.w);
        e_cur = e_next;
        buf ^= 1;
    }

    // ---- encode_b = logsumexp_j(fs[j] + T[j][PAD]) ----
    float4 x;
    x.x = fs.x + T[(j0 + 0) * CRF_L + PAD_ID];
    x.y = fs.y + T[(j0 + 1) * CRF_L + PAD_ID];
    x.z = fs.z + T[(j0 + 2) * CRF_L + PAD_ID];
    x.w = fs.w + T[(j0 + 3) * CRF_L + PAD_ID];
    float mm = fmaxf(fmaxf(x.x, x.y), fmaxf(x.z, x.w));
    #pragma unroll
    for (int o = 16; o; o >>= 1) mm = fmaxf(mm, __shfl_xor_sync(0xffffffffu, mm, o));
    float s = __expf(x.x - mm) + __expf(x.y - mm) + __expf(x.z - mm) + __expf(x.w - mm);
    #pragma unroll
    for (int o = 16; o; o >>= 1) s += __shfl_xor_sync(0xffffffffu, s, o);
    float r = mm + __logf(s);

    if (lane == 0) atomicAdd(out, r - gold - ends);
}

// ---------------------------------------------------------------------------
extern "C" void kernel_launch(void* const* d_in, const int* in_sizes, int n_in,
                              void* d_out, int out_size) {
    const float* emit   = (const float*)d_in[0];
    const int*   labels = (const int*)d_in[1];
    const void*  masks  = d_in[2];
    const float* T      = (const float*)d_in[3];
    float* out = (float*)d_out;

    (void)in_sizes; (void)n_in; (void)out_size;

    cudaFuncSetAttribute(crf_main, cudaFuncAttributeMaxDynamicSharedMemorySize, 70 * 1024);

    crf_prep<<<1, 256>>>((const unsigned*)masks, out);

    size_t smem = (CRF_L * CRF_L + 2 * 2 * CRF_L) * sizeof(float);  // expT + 2 warp p-buffers
    crf_main<<<CRF_B / 2, 64, smem>>>(emit, labels, masks, T, out);
}

// round 3
// speedup vs baseline: 3.1390x; 3.1390x over previous
#include <cuda_runtime.h>
#include <cstdint>

#define CRF_S 512
#define CRF_B 256
#define CRF_L 128
#define PAD_ID 0
#define START_ID 1

typedef unsigned long long ull;

// mask dtype: 0 = int32, 1 = byte(bool/int8), 2 = float32
__device__ int g_mode;

// ---------------------------------------------------------------------------
// Prep: detect mask dtype (deterministic fingerprint) and zero the output.
// ---------------------------------------------------------------------------
__global__ void crf_prep(const unsigned* __restrict__ masks_w, float* out) {
    __shared__ int flagByte, flagFloat;
    int tid = threadIdx.x;
    if (tid == 0) { flagByte = 0; flagFloat = 0; out[0] = 0.0f; }
    __syncthreads();
    int lb = 0, lf = 0;
    for (int k = tid; k < (CRF_B * CRF_S) / 4; k += blockDim.x) {
        unsigned w = masks_w[k];
        if (w == 0x3F800000u) lf = 1;          // float 1.0 pattern
        else if (w > 1u) lb = 1;               // byte-packed bools
    }
    if (lb) atomicOr(&flagByte, 1);
    if (lf) atomicOr(&flagFloat, 1);
    __syncthreads();
    if (tid == 0) g_mode = flagFloat ? 2 : (flagByte ? 1 : 0);
}

// ---- packed f32x2 helpers ----
__device__ __forceinline__ ull fma2(ull a, ull b, ull c) {
    ull d;
    asm("fma.rn.f32x2 %0, %1, %2, %3;" : "=l"(d) : "l"(a), "l"(b), "l"(c));
    return d;
}
__device__ __forceinline__ ull pack2(float lo, float hi) {
    ull r; asm("mov.b64 %0, {%1, %2};" : "=l"(r) : "f"(lo), "f"(hi)); return r;
}
__device__ __forceinline__ float2 unpack2(ull v) {
    float2 r; asm("mov.b64 {%0, %1}, %2;" : "=f"(r.x), "=f"(r.y) : "l"(v)); return r;
}

// group barrier: 128 threads, named barrier id = group+1
#define GBAR(id) asm volatile("bar.sync %0, 128;" :: "r"(id) : "memory")

// ---------------------------------------------------------------------------
// Main: 128 blocks x 256 threads. Each block hosts TWO independent 128-thread
// groups (one batch each) synced by named barriers. Thread j of a group owns
// column j of expT = exp(T), held in 64 packed f32x2 registers.
// Per step: p = exp(fs - m_lag) -> smem broadcast; dot_j via 64 fma.rn.f32x2;
// fs_j = e_t[j] + m_lag + log(dot_j). Max reduction runs one step lagged
// (logsumexp is exact for any shift; lag only affects overflow headroom).
// ---------------------------------------------------------------------------
__global__ void __launch_bounds__(256, 1) crf_main(
    const float* __restrict__ emit,
    const int*   __restrict__ labels,
    const void*  __restrict__ masks,
    const float* __restrict__ T,
    float* out)
{
    __shared__ float sm_p[2][2][CRF_L];     // [group][buf][i]
    __shared__ float sm_wmax[2][2][4];      // [group][buf][warp]

    int tid  = threadIdx.x;
    int grp  = tid >> 7;            // 0 or 1
    int gt   = tid & 127;           // thread-in-group == column j
    int warp = (gt >> 5);           // warp within group (0..3)
    int lane = tid & 31;
    int b    = blockIdx.x * 2 + grp;
    int barid = grp + 1;

    // ---- expT column j -> 64 packed register pairs ----
    ull mat[64];
    #pragma unroll
    for (int k = 0; k < 64; k++) {
        float lo = __expf(T[(2 * k)     * CRF_L + gt]);
        float hi = __expf(T[(2 * k + 1) * CRF_L + gt]);
        mat[k] = pack2(lo, hi);
    }

    // ---- length from masks (prefix-structured); each warp computes redundantly ----
    int mode = g_mode;
    int cnt = 0;
    if (mode == 1) {
        const unsigned char* mb = (const unsigned char*)masks + (size_t)b * CRF_S;
        for (int k = lane; k < CRF_S; k += 32) cnt += (mb[k] != 0);
    } else if (mode == 2) {
        const float* mf = (const float*)masks + (size_t)b * CRF_S;
        for (int k = lane; k < CRF_S; k += 32) cnt += (mf[k] != 0.0f);
    } else {
        const int* mi = (const int*)masks + (size_t)b * CRF_S;
        for (int k = lane; k < CRF_S; k += 32) cnt += (mi[k] != 0);
    }
    #pragma unroll
    for (int o = 16; o; o >>= 1) cnt += __shfl_xor_sync(0xffffffffu, cnt, o);
    int len = cnt < 1 ? 1 : cnt;

    // ---- gold path (warp 0 of each group; result lives in lane 0 == gt 0) ----
    float gold = 0.f, ends = 0.f;
    if (warp == 0) {
        for (int t = lane; t < len; t += 32) {
            int lab  = labels[b * CRF_S + t];
            int prev = (t == 0) ? START_ID : labels[b * CRF_S + t - 1];
            gold += emit[((size_t)t * CRF_B + b) * CRF_L + lab] + T[prev * CRF_L + lab];
        }
        #pragma unroll
        for (int o = 16; o; o >>= 1) gold += __shfl_xor_sync(0xffffffffu, gold, o);
        ends = T[labels[b * CRF_S + (len - 1)] * CRF_L + PAD_ID];
    }

    // ---- init: fs_j = emit[0][b][j] + T[START][j] ----
    float fs = emit[(size_t)b * CRF_L + gt] + T[START_ID * CRF_L + gt];

    // exact max(fs0) via slot buf=0
    float m;
    {
        float wm = fs;
        #pragma unroll
        for (int o = 16; o; o >>= 1) wm = fmaxf(wm, __shfl_xor_sync(0xffffffffu, wm, o));
        if (lane == 0) sm_wmax[grp][0][warp] = wm;
        GBAR(barid);
        float4 wv = *reinterpret_cast<float4*>(sm_wmax[grp][0]);
        m = fmaxf(fmaxf(wv.x, wv.y), fmaxf(wv.z, wv.w));
    }

    // ---- emit prefetch pipeline (depth 2), pointer-increment addressing ----
    const float* ep = emit + (size_t)CRF_B * CRF_L + b * CRF_L + gt;   // t=1
    const long estride = (long)CRF_B * CRF_L;
    float e_cur = 0.f, e_n = 0.f;
    if (len > 1) e_cur = ep[0];
    if (len > 2) e_n   = ep[estride];

    // ---- forward scan ----
    int buf = 1;   // first loop write goes to buf 1 (buf 0 just consumed above)
    for (int t = 1; t < len; t++) {
        // publish p = exp(fs - m_lag) and this step's warp-max (consumed next step)
        float p = __expf(fs - m);
        sm_p[grp][buf][gt] = p;
        float wm = fs;
        #pragma unroll
        for (int o = 16; o; o >>= 1) wm = fmaxf(wm, __shfl_xor_sync(0xffffffffu, wm, o));
        if (lane == 0) sm_wmax[grp][buf][warp] = wm;

        float e_f = 0.f;
        if (t + 2 < len) e_f = ep[2 * estride];   // prefetch emit[t+2]

        GBAR(barid);

        // next-step shift (lag-1 max)
        float4 wv = *reinterpret_cast<float4*>(sm_wmax[grp][buf]);
        float mN = fmaxf(fmaxf(wv.x, wv.y), fmaxf(wv.z, wv.w));

        // dot_j = sum_i p[i] * expT[i][j]   (64 packed FMA2, 4 chains)
        const ulonglong2* pb2 = reinterpret_cast<const ulonglong2*>(sm_p[grp][buf]);
        ull a0 = 0, a1 = 0, a2 = 0, a3 = 0;
        #pragma unroll
        for (int k = 0; k < 32; k += 2) {
            ulonglong2 pA = pb2[k];
            ulonglong2 pB = pb2[k + 1];
            a0 = fma2(pA.x, mat[2 * k],     a0);
            a1 = fma2(pA.y, mat[2 * k + 1], a1);
            a2 = fma2(pB.x, mat[2 * k + 2], a2);
            a3 = fma2(pB.y, mat[2 * k + 3], a3);
        }
        float2 f0 = unpack2(a0), f1 = unpack2(a1), f2 = unpack2(a2), f3 = unpack2(a3);
        float dot = ((f0.x + f0.y) + (f1.x + f1.y)) + ((f2.x + f2.y) + (f3.x + f3.y));

        fs = e_cur + m + __logf(dot);

        m = mN;
        e_cur = e_n; e_n = e_f;
        ep += estride;
        buf ^= 1;
    }

    // ---- encode_b = logsumexp_j(fs[j] + T[j][PAD]) ----
    GBAR(barid);   // quiesce last loop iteration's smem traffic
    float x = fs + T[gt * CRF_L + PAD_ID];
    float wm = x;
    #pragma unroll
    for (int o = 16; o; o >>= 1) wm = fmaxf(wm, __shfl_xor_sync(0xffffffffu, wm, o));
    if (lane == 0) sm_wmax[grp][0][warp] = wm;
    GBAR(barid);
    float4 wv = *reinterpret_cast<float4*>(sm_wmax[grp][0]);
    float mm = fmaxf(fmaxf(wv.x, wv.y), fmaxf(wv.z, wv.w));
    float s = __expf(x - mm);
    #pragma unroll
    for (int o = 16; o; o >>= 1) s += __shfl_xor_sync(0xffffffffu, s, o);
    if (lane == 0) sm_wmax[grp][1][warp] = s;
    GBAR(barid);
    if (gt == 0) {
        float4 sv = *reinterpret_cast<float4*>(sm_wmax[grp][1]);
        float r = mm + __logf(sv.x + sv.y + sv.z + sv.w);
        atomicAdd(out, r - gold - ends);
    }
}

// ---------------------------------------------------------------------------
extern "C" void kernel_launch(void* const* d_in, const int* in_sizes, int n_in,
                              void* d_out, int out_size) {
    const float* emit   = (const float*)d_in[0];
    const int*   labels = (const int*)d_in[1];
    const void*  masks  = d_in[2];
    const float* T      = (const float*)d_in[3];
    float* out = (float*)d_out;

    (void)in_sizes; (void)n_in; (void)out_size;

    crf_prep<<<1, 256>>>((const unsigned*)masks, out);
    crf_main<<<CRF_B / 2, 256>>>(emit, labels, masks, T, out);
}

// round 5
// speedup vs baseline: 3.3497x; 1.0671x over previous
#include <cuda_runtime.h>
#include <cstdint>

#define CRF_S 512
#define CRF_B 256
#define CRF_L 128
#define PAD_ID 0
#define START_ID 1

typedef unsigned long long ull;

// mask dtype: 0 = int32, 1 = byte(bool/int8), 2 = float32
__device__ int g_mode;

// ---------------------------------------------------------------------------
// Prep: detect mask dtype (deterministic fingerprint) and zero the output.
// ---------------------------------------------------------------------------
__global__ void crf_prep(const unsigned* __restrict__ masks_w, float* out) {
    __shared__ int flagByte, flagFloat;
    int tid = threadIdx.x;
    if (tid == 0) { flagByte = 0; flagFloat = 0; out[0] = 0.0f; }
    __syncthreads();
    int lb = 0, lf = 0;
    for (int k = tid; k < (CRF_B * CRF_S) / 4; k += blockDim.x) {
        unsigned w = masks_w[k];
        if (w == 0x3F800000u) lf = 1;          // float 1.0 pattern
        else if (w > 1u) lb = 1;               // byte-packed bools
    }
    if (lb) atomicOr(&flagByte, 1);
    if (lf) atomicOr(&flagFloat, 1);
    __syncthreads();
    if (tid == 0) g_mode = flagFloat ? 2 : (flagByte ? 1 : 0);
}

// ---- packed f32x2 helpers ----
__device__ __forceinline__ ull fma2(ull a, ull b, ull c) {
    ull d;
    asm("fma.rn.f32x2 %0, %1, %2, %3;" : "=l"(d) : "l"(a), "l"(b), "l"(c));
    return d;
}
__device__ __forceinline__ ull add2(ull a, ull b) {
    ull d;
    asm("add.rn.f32x2 %0, %1, %2;" : "=l"(d) : "l"(a), "l"(b));
    return d;
}
__device__ __forceinline__ ull pack2(float lo, float hi) {
    ull r; asm("mov.b64 %0, {%1, %2};" : "=l"(r) : "f"(lo), "f"(hi)); return r;
}
__device__ __forceinline__ float2 unpack2(ull v) {
    float2 r; asm("mov.b64 {%0, %1}, %2;" : "=f"(r.x), "=f"(r.y) : "l"(v)); return r;
}

// group barrier: 128 threads, named barrier id = group+1
#define GBAR(id) asm volatile("bar.sync %0, 128;" :: "r"(id) : "memory")

// ---------------------------------------------------------------------------
// Main: 128 blocks x 256 threads; two independent 128-thread groups per block
// (one batch each, named barriers). Thread j owns column j of expT = exp(T)
// in 64 packed f32x2 registers.
// Per step: shift m = fs[0] from the PREVIOUS step (logsumexp is shift-exact;
// fs spread + 1-step drift << 88, so exp never overflows). No max reduction.
// p = exp(fs - m) -> smem; dot_j = sum_i p[i]*expT[i][j] via 64 fma.rn.f32x2
// in 8 chains; fs_j = e_t[j] + m + log(dot_j). One bar.sync per step.
// ---------------------------------------------------------------------------
__global__ void __launch_bounds__(256, 1) crf_main(
    const float* __restrict__ emit,
    const int*   __restrict__ labels,
    const void*  __restrict__ masks,
    const float* __restrict__ T,
    float* out)
{
    __shared__ __align__(16) float sm_p[2][2][CRF_L];   // [group][buf][i]
    __shared__ float sm_m[2][2];                        // [group][buf] shift scalar
    __shared__ float sm_red[2][2][4];                   // final reduction scratch

    int tid  = threadIdx.x;
    int grp  = tid >> 7;            // 0 or 1
    int gt   = tid & 127;           // thread-in-group == column j
    int lane = tid & 31;
    int b    = blockIdx.x * 2 + grp;
    int barid = grp + 1;

    // ---- expT column j -> 64 packed register pairs ----
    ull mat[64];
    #pragma unroll
    for (int k = 0; k < 64; k++) {
        float lo = __expf(T[(2 * k)     * CRF_L + gt]);
        float hi = __expf(T[(2 * k + 1) * CRF_L + gt]);
        mat[k] = pack2(lo, hi);
    }

    // ---- length from masks (prefix-structured); per-warp redundant ----
    int mode = g_mode;
    int cnt = 0;
    if (mode == 1) {
        const unsigned char* mb = (const unsigned char*)masks + (size_t)b * CRF_S;
        for (int k = lane; k < CRF_S; k += 32) cnt += (mb[k] != 0);
    } else if (mode == 2) {
        const float* mf = (const float*)masks + (size_t)b * CRF_S;
        for (int k = lane; k < CRF_S; k += 32) cnt += (mf[k] != 0.0f);
    } else {
        const int* mi = (const int*)masks + (size_t)b * CRF_S;
        for (int k = lane; k < CRF_S; k += 32) cnt += (mi[k] != 0);
    }
    #pragma unroll
    for (int o = 16; o; o >>= 1) cnt += __shfl_xor_sync(0xffffffffu, cnt, o);
    int len = cnt < 1 ? 1 : cnt;

    // ---- gold path (warp 0 of each group) ----
    float gold = 0.f, ends = 0.f;
    if ((gt >> 5) == 0) {
        for (int t = lane; t < len; t += 32) {
            int lab  = labels[b * CRF_S + t];
            int prev = (t == 0) ? START_ID : labels[b * CRF_S + t - 1];
            gold += emit[((size_t)t * CRF_B + b) * CRF_L + lab] + T[prev * CRF_L + lab];
        }
        #pragma unroll
        for (int o = 16; o; o >>= 1) gold += __shfl_xor_sync(0xffffffffu, gold, o);
        ends = T[labels[b * CRF_S + (len - 1)] * CRF_L + PAD_ID];
    }

    // ---- init: fs_j = emit[0][b][j] + T[START][j]; shift = fs[0] ----
    float fs = emit[(size_t)b * CRF_L + gt] + T[START_ID * CRF_L + gt];
    if (gt == 0) sm_m[grp][0] = fs;
    GBAR(barid);
    float m = sm_m[grp][0];

    // ---- emit prefetch pipeline (depth 2) ----
    const float* ep = emit + (size_t)CRF_B * CRF_L + b * CRF_L + gt;   // t=1
    const long estride = (long)CRF_B * CRF_L;
    float e_cur = 0.f, e_n = 0.f;
    if (len > 1) e_cur = ep[0];
    if (len > 2) e_n   = ep[estride];

    // ---- forward scan ----
    int buf = 1;
    for (int t = 1; t < len; t++) {
        // publish p = exp(fs - m) and this step's shift source (fs[0])
        float p = __expf(fs - m);
        sm_p[grp][buf][gt] = p;
        if (gt == 0) sm_m[grp][buf] = fs;

        float e_f = 0.f;
        if (t + 2 < len) e_f = ep[2 * estride];   // prefetch emit[t+2]

        GBAR(barid);

        float mN = sm_m[grp][buf];                // next-step shift (lag-1)

        // dot_j = sum_i p[i] * expT[i][j]  (64 packed FMA2, 8 chains)
        const ulonglong2* pb2 = reinterpret_cast<const ulonglong2*>(sm_p[grp][buf]);
        ull a0 = 0, a1 = 0, a2 = 0, a3 = 0, a4 = 0, a5 = 0, a6 = 0, a7 = 0;
        #pragma unroll
        for (int k = 0; k < 32; k += 4) {
            ulonglong2 pA = pb2[k];
            ulonglong2 pB = pb2[k + 1];
            ulonglong2 pC = pb2[k + 2];
            ulonglong2 pD = pb2[k + 3];
            a0 = fma2(pA.x, mat[2 * k],     a0);
            a1 = fma2(pA.y, mat[2 * k + 1], a1);
            a2 = fma2(pB.x, mat[2 * k + 2], a2);
            a3 = fma2(pB.y, mat[2 * k + 3], a3);
            a4 = fma2(pC.x, mat[2 * k + 4], a4);
            a5 = fma2(pC.y, mat[2 * k + 5], a5);
            a6 = fma2(pD.x, mat[2 * k + 6], a6);
            a7 = fma2(pD.y, mat[2 * k + 7], a7);
        }
        // packed reduction tree: 7 add.f32x2 + 1 unpack + 1 add
        a0 = add2(a0, a1); a2 = add2(a2, a3); a4 = add2(a4, a5); a6 = add2(a6, a7);
        a0 = add2(a0, a2); a4 = add2(a4, a6);
        a0 = add2(a0, a4);
        float2 f0 = unpack2(a0);
        float dot = f0.x + f0.y;

        fs = e_cur + m + __logf(dot);

        m = mN;
        e_cur = e_n; e_n = e_f;
        ep += estride;
        buf ^= 1;
    }

    // ---- encode_b = logsumexp_j(fs[j] + T[j][PAD]) ----
    GBAR(barid);   // quiesce last iteration's smem traffic
    float x = fs + T[gt * CRF_L + PAD_ID];
    float wm = x;
    #pragma unroll
    for (int o = 16; o; o >>= 1) wm = fmaxf(wm, __shfl_xor_sync(0xffffffffu, wm, o));
    if (lane == 0) sm_red[grp][0][gt >> 5] = wm;
    GBAR(barid);
    float4 wv = *reinterpret_cast<float4*>(sm_red[grp][0]);
    float mm = fmaxf(fmaxf(wv.x, wv.y), fmaxf(wv.z, wv.w));
    float s = __expf(x - mm);
    #pragma unroll
    for (int o = 16; o; o >>= 1) s += __shfl_xor_sync(0xffffffffu, s, o);
    if (lane == 0) sm_red[grp][1][gt >> 5] = s;
    GBAR(barid);
    if (gt == 0) {
        float4 sv = *reinterpret_cast<float4*>(sm_red[grp][1]);
        float r = mm + __logf(sv.x + sv.y + sv.z + sv.w);
        atomicAdd(out, r - gold - ends);
    }
}

// ---------------------------------------------------------------------------
extern "C" void kernel_launch(void* const* d_in, const int* in_sizes, int n_in,
                              void* d_out, int out_size) {
    const float* emit   = (const float*)d_in[0];
    const int*   labels = (const int*)d_in[1];
    const void*  masks  = d_in[2];
    const float* T      = (const float*)d_in[3];
    float* out = (float*)d_out;

    (void)in_sizes; (void)n_in; (void)out_size;

    crf_prep<<<1, 256>>>((const unsigned*)masks, out);
    crf_main<<<CRF_B / 2, 256>>>(emit, labels, masks, T, out);
}